// round 15
// baseline (speedup 1.0000x reference)
#include <cuda_runtime.h>
#include <cuda_fp16.h>

#define BLOCK   128
#define WPB     4
#define NSM     152
#define OCC     6
#define NBLOCKS (NSM * OCC)          // 912
#define NWARPS  (NBLOCKS * WPB)      // 3648 chunks, 1 per warp
#define WARM    8
#define XSP     20                   // xs row stride (floats): 80B, 16B-aligned
#define MSP     33                   // ms row stride (float2): bank-staggered
#define PSP     36

typedef unsigned int u32;

__device__ __forceinline__ float ftanh(float x) {
    float r; asm("tanh.approx.f32 %0, %1;" : "=f"(r) : "f"(x)); return r;
}
__device__ __forceinline__ void cpa16(unsigned d, const void* s) {
    asm volatile("cp.async.ca.shared.global [%0], [%1], 16;" :: "r"(d), "l"(s));
}
__device__ __forceinline__ void cpacommit() { asm volatile("cp.async.commit_group;"); }
__device__ __forceinline__ void cpawait0()  { asm volatile("cp.async.wait_group 0;"); }
__device__ __forceinline__ u32 h2(float lo, float hi) {
    __half2 h = __floats2half2_rn(lo, hi);
    return *reinterpret_cast<u32*>(&h);
}
// D(16x8,f32) = A(16x16,f16,row) * B(16x8,f16,col) + C
__device__ __forceinline__ void mma16816(
    float& d0, float& d1, float& d2, float& d3,
    u32 a0, u32 a1, u32 a2, u32 a3, u32 b0, u32 b1,
    float c0, float c1, float c2, float c3)
{
    asm volatile(
        "mma.sync.aligned.m16n8k16.row.col.f32.f16.f16.f32 "
        "{%0,%1,%2,%3}, {%4,%5,%6,%7}, {%8,%9}, {%10,%11,%12,%13};"
        : "=f"(d0), "=f"(d1), "=f"(d2), "=f"(d3)
        : "r"(a0), "r"(a1), "r"(a2), "r"(a3), "r"(b0), "r"(b1),
          "f"(c0), "f"(c1), "f"(c2), "f"(c3));
}

__global__ void __launch_bounds__(BLOCK, OCC) rnn_mma_kernel(
    const float* __restrict__ x, const float* __restrict__ weight,
    const float* __restrict__ weight_y, const float* __restrict__ bias,
    const float* __restrict__ weight_ln, const float* __restrict__ bias_ln,
    float* __restrict__ out, int B, int L)
{
    __shared__ __align__(16) float  xs[WPB][2][16][XSP];  // x tiles, double-buffered
    __shared__ __align__(16) float2 ms[WPB][16][MSP];     // m pairs (step-major)
    __shared__ __align__(16) float  ps[WPB][16][PSP];     // scan partials

    const int w    = threadIdx.x >> 5;
    const int lane = threadIdx.x & 31;
    const int wid  = blockIdx.x * WPB + w;
    const int start = wid * L;
    if (start >= B) return;
    const int tstop = min(start + L, B);
    const int t0    = max(0, start - WARM);   // contraction warmup (<=0.25^8)
    const int nt    = (tstop - t0 + 15) >> 4;

    // sigma(y) = 0.5 + 0.5*tanh(y/2); z = y/2; state t = tanh(z):
    //   z = (0.5*bias + 0.25*wy_h) + x·(0.5 W) + (0.25*wy_h)*t
    const float SC = 0.5f;

    // ── mma fragment constants (g = lane/4 owns rows g,g+8 / col g; t4 = lane%4)
    const int g  = lane >> 2;
    const int t4 = lane & 3;
    u32  wb0[8], wb1[8];    // B frags per n-tile T (cols 8T..8T+7 = hidden)
    float cb0[8], cb1[8];   // C bias per n-tile (depends on hidden col only)
    const float bc = SC * bias[0];
#pragma unroll
    for (int T = 0; T < 8; T++) {
        const int hc = 8 * T + g;                 // B col = hidden index
        wb0[T] = h2(SC * weight[(2 * t4)     * 64 + hc], SC * weight[(2 * t4 + 1) * 64 + hc]);
        wb1[T] = h2(SC * weight[(2 * t4 + 8) * 64 + hc], SC * weight[(2 * t4 + 9) * 64 + hc]);
        const int hp = 8 * T + 2 * t4;            // D col pair = hidden pair
        cb0[T] = bc + 0.25f * weight_y[hp];
        cb1[T] = bc + 0.25f * weight_y[hp + 1];
    }

    // ── scan constants: lane owns hidden pair (2*lane, 2*lane+1)
    const int h0 = 2 * lane, h1 = 2 * lane + 1;
    const float wyt0 = 0.25f * weight_y[h0];
    const float wyt1 = 0.25f * weight_y[h1];
    const float hl0  = 0.5f * weight_ln[h0];
    const float hl1  = 0.5f * weight_ln[h1];
    const float hsum = hl0 + hl1;
    const float bln  = bias_ln[0];

    float z0 = 0.f, z1 = 0.f;
    float t0s = -1.f, t1s = -1.f;    // t = 2s-1; s_init = 0 -> t = -1

    auto issue = [&](int tb, int st) {
#pragma unroll
        for (int r = 0; r < 2; r++) {
            int slot = lane + r * 32;             // 64 slots = 16 rows x 4 quarters
            int row = slot >> 2, q = slot & 3;
            int t = min(tb + row, B - 1);
            cpa16((unsigned)__cvta_generic_to_shared(&xs[w][st][row][q * 4]),
                  x + (size_t)t * 64 + q * 4);
        }
    };

    const int jj   = lane & 15;
    const int half = lane >> 4;
    auto reducePS = [&](int tb_) {
        const float4* pr = (const float4*)(&ps[w][jj][half * 16]);
        float4 a0 = pr[0], a1 = pr[1], a2 = pr[2], a3 = pr[3];
        float r0 = ((a0.x + a0.y) + (a0.z + a0.w)) + ((a1.x + a1.y) + (a1.z + a1.w));
        float r1 = ((a2.x + a2.y) + (a2.z + a2.w)) + ((a3.x + a3.y) + (a3.z + a3.w));
        float r = r0 + r1;
        r += __shfl_xor_sync(0xffffffffu, r, 16);
        int t = tb_ + jj;
        if (half == 0 && t >= start && t < tstop)
            out[t] = bln + r;
    };

    // Prologue
    issue(t0, 0);
    cpacommit();
    cpawait0();
    __syncwarp();

    int tb = t0;

    for (int k = 0; k < nt; k++) {
        const int st = k & 1;
        if (k + 1 < nt) { issue(tb + 16, st ^ 1); cpacommit(); }

        // ── A fragment from this tile's x (fp32 -> fp16): rows g, g+8
        const float (*xa)[XSP] = xs[w][st];
        float2 f0 = *(const float2*)&xa[g][2 * t4];
        float2 f1 = *(const float2*)&xa[g + 8][2 * t4];
        float2 f2 = *(const float2*)&xa[g][2 * t4 + 8];
        float2 f3 = *(const float2*)&xa[g + 8][2 * t4 + 8];
        u32 A0 = h2(f0.x, f0.y), A1 = h2(f1.x, f1.y);
        u32 A2 = h2(f2.x, f2.y), A3 = h2(f3.x, f3.y);

        // ── 8 HMMA: m[16 steps][64 hidden], then transpose to step-major smem
#pragma unroll
        for (int T = 0; T < 8; T++) {
            float d0, d1, d2, d3;
            mma16816(d0, d1, d2, d3, A0, A1, A2, A3, wb0[T], wb1[T],
                     cb0[T], cb1[T], cb0[T], cb1[T]);
            ms[w][g][4 * T + t4]     = make_float2(d0, d1);   // step g
            ms[w][g + 8][4 * T + t4] = make_float2(d2, d3);   // step g+8
        }
        __syncwarp();

        // ── scan: 16 serial steps, m prefetched one step ahead
        const int n = min(16, tstop - tb);
        if (n == 16) {
            float2 mu = ms[w][0][lane];
#pragma unroll
            for (int j = 0; j < 16; j++) {
                float2 mn;
                if (j < 15) mn = ms[w][j + 1][lane];
                z0 = fmaf(wyt0, t0s, mu.x);
                z1 = fmaf(wyt1, t1s, mu.y);
                t0s = ftanh(z0);
                t1s = ftanh(z1);
                ps[w][j][lane] = fmaf(hl1, t1s, fmaf(hl0, t0s, hsum));
                if (j < 15) mu = mn;
            }
        } else {
            for (int j = 0; j < n; j++) {
                float2 mu = ms[w][j][lane];
                z0 = fmaf(wyt0, t0s, mu.x);
                z1 = fmaf(wyt1, t1s, mu.y);
                t0s = ftanh(z0);
                t1s = ftanh(z1);
                ps[w][j][lane] = fmaf(hl1, t1s, fmaf(hl0, t0s, hsum));
            }
        }
        __syncwarp();

        reducePS(tb);   // outputs of this tile (guarded by [start, tstop))

        if (k + 1 < nt) {
            cpawait0();
            __syncwarp();   // xs buffer ready; also orders ps/ms reuse
        }
        tb += 16;
    }

    // Unique last chunk writes final carries: y_h = 2z, y_hs = 0.5 + 0.5*t
    if (start + L >= B) {
        *(float2*)(out + B + 2 * lane) = make_float2(2.f * z0, 2.f * z1);
        *(float2*)(out + B + 64 + 2 * lane) =
            make_float2(fmaf(0.5f, t0s, 0.5f), fmaf(0.5f, t1s, 0.5f));
    }
}

extern "C" void kernel_launch(void* const* d_in, const int* in_sizes, int n_in,
                              void* d_out, int out_size)
{
    const float* x   = (const float*)d_in[0];
    const float* wt  = (const float*)d_in[1];
    const float* wy  = (const float*)d_in[2];
    const float* b   = (const float*)d_in[3];
    const float* wln = (const float*)d_in[4];
    const float* bln = (const float*)d_in[5];
    float* out = (float*)d_out;

    const int B = in_sizes[0] / 64;              // x is (B, T=4, I=16); row stride 64
    const int L = (B + NWARPS - 1) / NWARPS;     // steps per chunk

    rnn_mma_kernel<<<NBLOCKS, BLOCK>>>(x, wt, wy, b, wln, bln, out, B, L);
}

// round 16
// speedup vs baseline: 1.5567x; 1.5567x over previous
#include <cuda_runtime.h>
#include <cuda_fp16.h>

#define BLOCK   128
#define WPB     4
#define NSM     152
#define OCC     5
#define NBLOCKS (NSM * OCC)          // 760
#define NWARPS  (NBLOCKS * WPB)      // 3040 chunks, 1 per warp
#define WARM    8
#define MSP     36                   // ms row stride (floats): bank = 4g+t4 bijection

typedef unsigned int u32;

__device__ __forceinline__ float ftanh(float x) {
    float r; asm("tanh.approx.f32 %0, %1;" : "=f"(r) : "f"(x)); return r;
}
__device__ __forceinline__ void cpa16(unsigned d, const void* s) {
    asm volatile("cp.async.ca.shared.global [%0], [%1], 16;" :: "r"(d), "l"(s));
}
__device__ __forceinline__ void cpacommit() { asm volatile("cp.async.commit_group;"); }
__device__ __forceinline__ void cpawait0()  { asm volatile("cp.async.wait_group 0;"); }
__device__ __forceinline__ u32 h2(float lo, float hi) {
    __half2 h = __floats2half2_rn(lo, hi);
    return *reinterpret_cast<u32*>(&h);
}
// D(16x8,f32) = A(16x16,f16,row) * B(16x8,f16,col) + C
__device__ __forceinline__ void mma16816(
    float& d0, float& d1, float& d2, float& d3,
    u32 a0, u32 a1, u32 a2, u32 a3, u32 b0, u32 b1,
    float c0, float c1, float c2, float c3)
{
    asm volatile(
        "mma.sync.aligned.m16n8k16.row.col.f32.f16.f16.f32 "
        "{%0,%1,%2,%3}, {%4,%5,%6,%7}, {%8,%9}, {%10,%11,%12,%13};"
        : "=f"(d0), "=f"(d1), "=f"(d2), "=f"(d3)
        : "r"(a0), "r"(a1), "r"(a2), "r"(a3), "r"(b0), "r"(b1),
          "f"(c0), "f"(c1), "f"(c2), "f"(c3));
}

__global__ void __launch_bounds__(BLOCK, OCC) rnn_mma2_kernel(
    const float* __restrict__ x, const float* __restrict__ weight,
    const float* __restrict__ weight_y, const float* __restrict__ bias,
    const float* __restrict__ weight_ln, const float* __restrict__ bias_ln,
    float* __restrict__ out, int B, int L)
{
    __shared__ __align__(16) float xs[WPB][2][16][16];    // x tiles (dense)   8KB
    __shared__ __align__(16) float ms0[WPB][2][16][MSP];  // m even hidden    18KB
    __shared__ __align__(16) float ms1[WPB][2][16][MSP];  // m odd hidden     18KB

    const int w    = threadIdx.x >> 5;
    const int lane = threadIdx.x & 31;
    const int wid  = blockIdx.x * WPB + w;
    const int start = wid * L;
    if (start >= B) return;
    const int tstop = min(start + L, B);
    const int t0    = max(0, start - WARM);   // contraction warmup (<=0.25^8)
    const int nt    = (tstop - t0 + 15) >> 4;

    // sigma(y) = 0.5 + 0.5*tanh(y/2); z = y/2; state t = tanh(z):
    //   z = (0.5*bias + 0.25*wy_h) + x·(0.5 W) + (0.25*wy_h)*t
    const float SC = 0.5f;

    // ── mma fragment constants (lane = (g, t4); g = lane/4, t4 = lane%4)
    const int g  = lane >> 2;
    const int t4 = lane & 3;
    u32  wb0[8], wb1[8];    // B frags per n-tile T (cols 8T..8T+7 = hidden)
    float cb0[8], cb1[8];   // C bias per n-tile (depends on hidden col only)
    const float bc = SC * bias[0];
#pragma unroll
    for (int T = 0; T < 8; T++) {
        const int hc = 8 * T + g;
        wb0[T] = h2(SC * weight[(2 * t4)     * 64 + hc], SC * weight[(2 * t4 + 1) * 64 + hc]);
        wb1[T] = h2(SC * weight[(2 * t4 + 8) * 64 + hc], SC * weight[(2 * t4 + 9) * 64 + hc]);
        const int hp = 8 * T + 2 * t4;
        cb0[T] = bc + 0.25f * weight_y[hp];
        cb1[T] = bc + 0.25f * weight_y[hp + 1];
    }

    // ── scan constants: lane owns hidden pair (2*lane, 2*lane+1)
    const int h0 = 2 * lane, h1 = 2 * lane + 1;
    const float wyt0 = 0.25f * weight_y[h0];
    const float wyt1 = 0.25f * weight_y[h1];
    const float hl0  = 0.5f * weight_ln[h0];
    const float hl1  = 0.5f * weight_ln[h1];
    const float hsum = hl0 + hl1;
    const float bln  = bias_ln[0];

    float z0 = 0.f, z1 = 0.f;
    float t0s = -1.f, t1s = -1.f;    // t = 2s-1; s_init = 0 -> t = -1

    auto issue = [&](int tb, int st) {
#pragma unroll
        for (int r = 0; r < 2; r++) {
            int slot = lane + r * 32;             // 64 slots = 16 rows x 4 quarters
            int row = slot >> 2, q = slot & 3;
            int t = min(tb + row, B - 1);
            cpa16((unsigned)__cvta_generic_to_shared(&xs[w][st][row][q * 4]),
                  x + (size_t)t * 64 + q * 4);
        }
    };

    // 8 HMMA over tile in xs[w][st] -> ms0/ms1[w][st] (conflict-free transpose)
    auto mmaTile = [&](int st) {
        const float (*xa)[16] = xs[w][st];
        float2 f0 = *(const float2*)&xa[g][2 * t4];
        float2 f1 = *(const float2*)&xa[g + 8][2 * t4];
        float2 f2 = *(const float2*)&xa[g][2 * t4 + 8];
        float2 f3 = *(const float2*)&xa[g + 8][2 * t4 + 8];
        u32 A0 = h2(f0.x, f0.y), A1 = h2(f1.x, f1.y);
        u32 A2 = h2(f2.x, f2.y), A3 = h2(f3.x, f3.y);
#pragma unroll
        for (int T = 0; T < 8; T++) {
            float d0, d1, d2, d3;
            mma16816(d0, d1, d2, d3, A0, A1, A2, A3, wb0[T], wb1[T],
                     cb0[T], cb1[T], cb0[T], cb1[T]);
            const int c = 4 * T + t4;             // bank(g*36 + c) = 4g+t4: bijective
            ms0[w][st][g][c]     = d0;            // step g,   hidden 2c
            ms1[w][st][g][c]     = d1;            // step g,   hidden 2c+1
            ms0[w][st][g + 8][c] = d2;            // step g+8
            ms1[w][st][g + 8][c] = d3;
        }
    };

    const int jj   = lane & 15;
    const int half = lane >> 4;
    // reduce reads the scan partials written IN-PLACE into ms0[st]
    auto reducePS = [&](int st, int tb_) {
        const float4* pr = (const float4*)(&ms0[w][st][jj][half * 16]);
        float4 a0 = pr[0], a1 = pr[1], a2 = pr[2], a3 = pr[3];
        float r0 = ((a0.x + a0.y) + (a0.z + a0.w)) + ((a1.x + a1.y) + (a1.z + a1.w));
        float r1 = ((a2.x + a2.y) + (a2.z + a2.w)) + ((a3.x + a3.y) + (a3.z + a3.w));
        float r = r0 + r1;
        r += __shfl_xor_sync(0xffffffffu, r, 16);
        int t = tb_ + jj;
        if (half == 0 && t >= start && t < tstop)
            out[t] = bln + r;
    };

    // Prologue: xs tile 0 -> ms buffer 0
    issue(t0, 0);
    cpacommit();
    cpawait0();
    __syncwarp();
    mmaTile(0);
    __syncwarp();

    int tb = t0;

    for (int k = 0; k < nt; k++) {
        const int st = k & 1;
        if (k + 1 < nt) { issue(tb + 16, st ^ 1); cpacommit(); }   // x DRAM under scan

        // ── scan tile k from ms[st]; partial written back into ms0[st][j][lane]
        const int n = min(16, tstop - tb);
        if (n == 16) {
#pragma unroll
            for (int j = 0; j < 16; j++) {
                float mu0 = ms0[w][st][j][lane];   // 1-phase LDS.32
                float mu1 = ms1[w][st][j][lane];
                z0 = fmaf(wyt0, t0s, mu0);
                z1 = fmaf(wyt1, t1s, mu1);
                t0s = ftanh(z0);
                t1s = ftanh(z1);
                ms0[w][st][j][lane] = fmaf(hl1, t1s, fmaf(hl0, t0s, hsum));
            }
        } else {
            for (int j = 0; j < n; j++) {
                float mu0 = ms0[w][st][j][lane];
                float mu1 = ms1[w][st][j][lane];
                z0 = fmaf(wyt0, t0s, mu0);
                z1 = fmaf(wyt1, t1s, mu1);
                t0s = ftanh(z0);
                t1s = ftanh(z1);
                ms0[w][st][j][lane] = fmaf(hl1, t1s, fmaf(hl0, t0s, hsum));
            }
        }
        __syncwarp();

        reducePS(st, tb);        // consumes ms0[st] partials
        __syncwarp();

        if (k + 1 < nt) {
            cpawait0();
            __syncwarp();
            mmaTile(st ^ 1);     // produce m for tile k+1 (other ms buffer)
            __syncwarp();
        }
        tb += 16;
    }

    // Unique last chunk writes final carries: y_h = 2z, y_hs = 0.5 + 0.5*t
    if (start + L >= B) {
        *(float2*)(out + B + 2 * lane) = make_float2(2.f * z0, 2.f * z1);
        *(float2*)(out + B + 64 + 2 * lane) =
            make_float2(fmaf(0.5f, t0s, 0.5f), fmaf(0.5f, t1s, 0.5f));
    }
}

extern "C" void kernel_launch(void* const* d_in, const int* in_sizes, int n_in,
                              void* d_out, int out_size)
{
    const float* x   = (const float*)d_in[0];
    const float* wt  = (const float*)d_in[1];
    const float* wy  = (const float*)d_in[2];
    const float* b   = (const float*)d_in[3];
    const float* wln = (const float*)d_in[4];
    const float* bln = (const float*)d_in[5];
    float* out = (float*)d_out;

    const int B = in_sizes[0] / 64;              // x is (B, T=4, I=16); row stride 64
    const int L = (B + NWARPS - 1) / NWARPS;     // steps per chunk

    rnn_mma2_kernel<<<NBLOCKS, BLOCK>>>(x, wt, wy, b, wln, bln, out, B, L);
}

// round 17
// speedup vs baseline: 1.6806x; 1.0795x over previous
#include <cuda_runtime.h>
#include <cuda_fp16.h>

#define BLOCK   128
#define WPB     4
#define NSM     152
#define OCC     6
#define NBLOCKS (NSM * OCC)          // 912
#define NWARPS  (NBLOCKS * WPB)      // 3648 chunks, 1 per warp
#define WARM    8
#define MSP     36                   // msu row stride (u32): conflict-free STS/LDS/reduce

typedef unsigned int u32;

__device__ __forceinline__ float ftanh(float x) {
    float r; asm("tanh.approx.f32 %0, %1;" : "=f"(r) : "f"(x)); return r;
}
__device__ __forceinline__ u32 h2(float lo, float hi) {
    __half2 h = __floats2half2_rn(lo, hi);
    return *reinterpret_cast<u32*>(&h);
}
__device__ __forceinline__ float2 uh2f(u32 u) {
    return __half22float2(*reinterpret_cast<__half2*>(&u));
}
// D(16x8,f32) = A(16x16,f16,row) * B(16x8,f16,col) + C
__device__ __forceinline__ void mma16816(
    float& d0, float& d1, float& d2, float& d3,
    u32 a0, u32 a1, u32 a2, u32 a3, u32 b0, u32 b1,
    float c0, float c1, float c2, float c3)
{
    asm volatile(
        "mma.sync.aligned.m16n8k16.row.col.f32.f16.f16.f32 "
        "{%0,%1,%2,%3}, {%4,%5,%6,%7}, {%8,%9}, {%10,%11,%12,%13};"
        : "=f"(d0), "=f"(d1), "=f"(d2), "=f"(d3)
        : "r"(a0), "r"(a1), "r"(a2), "r"(a3), "r"(b0), "r"(b1),
          "f"(c0), "f"(c1), "f"(c2), "f"(c3));
}

__global__ void __launch_bounds__(BLOCK, OCC) rnn_mma3_kernel(
    const float* __restrict__ x, const float* __restrict__ weight,
    const float* __restrict__ weight_y, const float* __restrict__ bias,
    const float* __restrict__ weight_ln, const float* __restrict__ bias_ln,
    float* __restrict__ out, int B, int L)
{
    // m tiles as fp16x2 per (step, lane-pair); scan overwrites slots with fp32
    // partial bits in place; reduce reads rows back as float4.
    __shared__ __align__(16) u32 msu[WPB][2][16][MSP];    // 18.4KB/block

    const int w    = threadIdx.x >> 5;
    const int lane = threadIdx.x & 31;
    const int wid  = blockIdx.x * WPB + w;
    const int start = wid * L;
    if (start >= B) return;
    const int tstop = min(start + L, B);
    const int t0    = max(0, start - WARM);   // contraction warmup (<=0.25^8)
    const int nt    = (tstop - t0 + 15) >> 4;

    // sigma(y) = 0.5 + 0.5*tanh(y/2); z = y/2; state t = tanh(z):
    //   z = (0.5*bias + 0.25*wy_h) + x·(0.5 W) + (0.25*wy_h)*t
    const float SC = 0.5f;

    // ── mma fragment constants (lane = (g, t4); g = lane/4, t4 = lane%4)
    const int g  = lane >> 2;
    const int t4 = lane & 3;
    u32  wb0[8], wb1[8];    // B frags per n-tile T (cols 8T..8T+7 = hidden)
    float cb0[8], cb1[8];   // C bias per n-tile (col-dependent)
    const float bc = SC * bias[0];
#pragma unroll
    for (int T = 0; T < 8; T++) {
        const int hc = 8 * T + g;
        wb0[T] = h2(SC * weight[(2 * t4)     * 64 + hc], SC * weight[(2 * t4 + 1) * 64 + hc]);
        wb1[T] = h2(SC * weight[(2 * t4 + 8) * 64 + hc], SC * weight[(2 * t4 + 9) * 64 + hc]);
        const int hp = 8 * T + 2 * t4;
        cb0[T] = bc + 0.25f * weight_y[hp];
        cb1[T] = bc + 0.25f * weight_y[hp + 1];
    }

    // ── scan constants: lane owns hidden pair (2*lane, 2*lane+1)
    const int h0 = 2 * lane, h1 = 2 * lane + 1;
    const float wyt0 = 0.25f * weight_y[h0];
    const float wyt1 = 0.25f * weight_y[h1];
    const float hl0  = 0.5f * weight_ln[h0];
    const float hl1  = 0.5f * weight_ln[h1];
    const float hsum = hl0 + hl1;
    const float bln  = bias_ln[0];

    float z0 = 0.f, z1 = 0.f;
    float t0s = -1.f, t1s = -1.f;    // t = 2s-1; s_init = 0 -> t = -1

    // A-fragment x data straight from gmem (no smem for x): 4 LDG.64 per tile,
    // prefetched one tile ahead. Rows clamped; garbage beyond tstop never used.
    float2 F0, F1, F2, F3;
    auto ldgA = [&](int tb) {
        const int r0 = min(tb + g,     B - 1);
        const int r1 = min(tb + g + 8, B - 1);
        F0 = *(const float2*)(x + (size_t)r0 * 64 + 2 * t4);
        F1 = *(const float2*)(x + (size_t)r1 * 64 + 2 * t4);
        F2 = *(const float2*)(x + (size_t)r0 * 64 + 2 * t4 + 8);
        F3 = *(const float2*)(x + (size_t)r1 * 64 + 2 * t4 + 8);
    };

    // 8 HMMA from register fragments -> msu[st] (fp16x2 packed, conflict-free)
    auto mmaTile = [&](int st) {
        u32 A0 = h2(F0.x, F0.y), A1 = h2(F1.x, F1.y);
        u32 A2 = h2(F2.x, F2.y), A3 = h2(F3.x, F3.y);
#pragma unroll
        for (int T = 0; T < 8; T++) {
            float d0, d1, d2, d3;
            mma16816(d0, d1, d2, d3, A0, A1, A2, A3, wb0[T], wb1[T],
                     cb0[T], cb1[T], cb0[T], cb1[T]);
            const int c = 4 * T + t4;          // bank(36g + c) bijective over warp
            msu[w][st][g][c]     = h2(d0, d1); // step g,   hidden pair 2c,2c+1
            msu[w][st][g + 8][c] = h2(d2, d3); // step g+8
        }
    };

    const int jj   = lane & 15;
    const int half = lane >> 4;
    // reduce reads fp32 partial bits written in place by the scan
    auto reducePS = [&](int st, int tb_) {
        const float4* pr = (const float4*)(&msu[w][st][jj][half * 16]);
        float4 a0 = pr[0], a1 = pr[1], a2 = pr[2], a3 = pr[3];
        float r0 = ((a0.x + a0.y) + (a0.z + a0.w)) + ((a1.x + a1.y) + (a1.z + a1.w));
        float r1 = ((a2.x + a2.y) + (a2.z + a2.w)) + ((a3.x + a3.y) + (a3.z + a3.w));
        float r = r0 + r1;
        r += __shfl_xor_sync(0xffffffffu, r, 16);
        int t = tb_ + jj;
        if (half == 0 && t >= start && t < tstop)
            out[t] = bln + r;
    };

    // Prologue: tile 0 m in msu[0]; tile 1 x prefetched
    ldgA(t0);
    mmaTile(0);
    ldgA(t0 + 16);
    __syncwarp();

    int tb = t0;

    for (int k = 0; k < nt; k++) {
        const int st = k & 1;

        // ── scan tile k: read fp16x2 m, overwrite slot with fp32 partial bits
        const int n = min(16, tstop - tb);
        if (n == 16) {
#pragma unroll
            for (int j = 0; j < 16; j++) {
                float2 mf = uh2f(msu[w][st][j][lane]);   // 1-phase LDS.32
                z0 = fmaf(wyt0, t0s, mf.x);
                z1 = fmaf(wyt1, t1s, mf.y);
                t0s = ftanh(z0);
                t1s = ftanh(z1);
                msu[w][st][j][lane] =
                    __float_as_uint(fmaf(hl1, t1s, fmaf(hl0, t0s, hsum)));
            }
        } else {
            for (int j = 0; j < n; j++) {
                float2 mf = uh2f(msu[w][st][j][lane]);
                z0 = fmaf(wyt0, t0s, mf.x);
                z1 = fmaf(wyt1, t1s, mf.y);
                t0s = ftanh(z0);
                t1s = ftanh(z1);
                msu[w][st][j][lane] =
                    __float_as_uint(fmaf(hl1, t1s, fmaf(hl0, t0s, hsum)));
            }
        }
        __syncwarp();

        reducePS(st, tb);          // consumes in-place partials of msu[st]
        __syncwarp();

        if (k + 1 < nt) {
            mmaTile(st ^ 1);       // m for tile k+1 (x regs loaded last iter)
            ldgA(tb + 32);         // prefetch x for tile k+2 (~450cyc lead)
            __syncwarp();
        }
        tb += 16;
    }

    // Unique last chunk writes final carries: y_h = 2z, y_hs = 0.5 + 0.5*t
    if (start + L >= B) {
        *(float2*)(out + B + 2 * lane) = make_float2(2.f * z0, 2.f * z1);
        *(float2*)(out + B + 64 + 2 * lane) =
            make_float2(fmaf(0.5f, t0s, 0.5f), fmaf(0.5f, t1s, 0.5f));
    }
}

extern "C" void kernel_launch(void* const* d_in, const int* in_sizes, int n_in,
                              void* d_out, int out_size)
{
    const float* x   = (const float*)d_in[0];
    const float* wt  = (const float*)d_in[1];
    const float* wy  = (const float*)d_in[2];
    const float* b   = (const float*)d_in[3];
    const float* wln = (const float*)d_in[4];
    const float* bln = (const float*)d_in[5];
    float* out = (float*)d_out;

    const int B = in_sizes[0] / 64;              // x is (B, T=4, I=16); row stride 64
    const int L = (B + NWARPS - 1) / NWARPS;     // steps per chunk

    rnn_mma3_kernel<<<NBLOCKS, BLOCK>>>(x, wt, wy, b, wln, bln, out, B, L);
}